// round 15
// baseline (speedup 1.0000x reference)
#include <cuda_runtime.h>
#include <cuda_fp16.h>
#include <cstdint>

#define DD 128
#define EPB 128        // edges (or nodes) per block; 128 threads / 4 warps

__device__ float  g_agg[50000 * 128];
__device__ __half g_h16[50000 * 128];
__device__ __half g_agg16[50000 * 128];
__device__ int    g_is64;
// 14 chunk images x 8192 halves (16KB): We1 0-3, We2 4-5, Wc1 6-7, Wn1 8-11, Wn2 12-13
__device__ __half g_wimg16[14 * 8192];

// ---------------- helpers ----------------
__device__ __forceinline__ uint32_t smem_u32(const void* p) {
    uint32_t a;
    asm("{ .reg .u64 t; cvta.to.shared.u64 t, %1; cvt.u32.u64 %0, t; }" : "=r"(a) : "l"(p));
    return a;
}
__device__ __forceinline__ float tanh_a(float x) {
    float y;
    asm("tanh.approx.f32 %0, %1;" : "=f"(y) : "f"(x));
    return y;
}
__device__ __forceinline__ float silu_f(float x) {
    float hx = 0.5f * x;
    return hx + hx * tanh_a(hx);
}
__device__ __forceinline__ int slot_of(int L) { return L ^ ((L >> 3) & 3); }

__device__ __forceinline__ uint4 lds128(uint32_t a) {
    uint4 v;
    asm volatile("ld.shared.v4.b32 {%0,%1,%2,%3}, [%4];"
                 : "=r"(v.x), "=r"(v.y), "=r"(v.z), "=r"(v.w) : "r"(a));
    return v;
}
__device__ __forceinline__ void mma16(float* c, uint4 a, uint32_t b0, uint32_t b1) {
    asm volatile(
        "mma.sync.aligned.m16n8k16.row.col.f32.f16.f16.f32 "
        "{%0,%1,%2,%3}, {%4,%5,%6,%7}, {%8,%9}, {%0,%1,%2,%3};"
        : "+f"(c[0]), "+f"(c[1]), "+f"(c[2]), "+f"(c[3])
        : "r"(a.x), "r"(a.y), "r"(a.z), "r"(a.w), "r"(b0), "r"(b1));
}
__device__ __forceinline__ uint32_t h2u(float lo, float hi) {
    __half2 h = __floats2half2_rn(lo, hi);
    return *reinterpret_cast<uint32_t*>(&h);
}
__device__ __forceinline__ float2 u2f2(uint32_t u) {
    __half2 h = *reinterpret_cast<__half2*>(&u);
    return __half22float2(h);
}
#define CP_ASYNC_4(dst, src) \
    asm volatile("cp.async.ca.shared.global [%0], [%1], 4;" :: "r"(dst), "l"(src) : "memory")
#define CP_ASYNC_16(dst, src) \
    asm volatile("cp.async.cg.shared.global [%0], [%1], 16;" :: "r"(dst), "l"(src) : "memory")
#define CP_COMMIT() asm volatile("cp.async.commit_group;" ::: "memory")
#define CP_WAIT(n)  asm volatile("cp.async.wait_group %0;" :: "n"(n) : "memory")

// ---------------- smem maps (bytes) ----------------
// XB: two 16KB K=64 layer-1 chunk slots. WB: two 16KB weight-chunk ring slots.
#define XB_B    0
#define WB_B    32768
#define SROW_B  65536
#define SCOL_B  66048
#define SDX_B   66560
#define SDY_B   67072
#define SDZ_B   67584
#define SID_B   68096
#define SDIST_B 68608
#define W257_B  69120
#define SWC2_B  69632
#define SBE1_B  70144
#define SBE2_B  70656
#define SBC1_B  71168
#define EDGE_SMEM_BYTES 71680

#define NWB_B   32768
#define NBN1_B  65536
#define NBN2_B  66048
#define NODE_SMEM_BYTES 66560

// ---------------- small kernels ----------------
__global__ void egnn_detect_kernel(const int* __restrict__ ei32) {
    int is64 = 1;
#pragma unroll
    for (int i = 1; i < 64; i += 2)
        if (ei32[i] != 0) is64 = 0;
    g_is64 = is64;
}

__global__ void egnn_init_kernel(const float* __restrict__ pos, const float* __restrict__ h,
                                 float* __restrict__ pos_out,
                                 long long nAgg, long long nPos) {
    long long i = (long long)blockIdx.x * blockDim.x + threadIdx.x;
    if (i < nAgg) { g_agg[i] = 0.0f; g_h16[i] = __float2half(h[i]); }
    if (i < nPos) pos_out[i] = pos[i];
}

__global__ void egnn_conv_agg(long long nAgg) {
    long long i = (long long)blockIdx.x * blockDim.x + threadIdx.x;
    if (i < nAgg) g_agg16[i] = __float2half(g_agg[i]);
}

// fp16 B-fragment chunk images (identical encoding to R9-R14 — proven).
__global__ void egnn_prep_w(const float* __restrict__ We1, const float* __restrict__ We2,
                            const float* __restrict__ Wc1, const float* __restrict__ Wn1,
                            const float* __restrict__ Wn2) {
    int i = blockIdx.x * 256 + threadIdx.x;
    if (i >= 14 * 8192) return;
    int ci = i >> 13;
    int r = i & 8191;
    int rec = r >> 8;
    int lane = (r >> 3) & 31;
    int sub = r & 7;
    int ntp = rec >> 2, ks = rec & 3;
    int g = lane >> 2, tig = lane & 3;
    int n = (ntp * 2 + (sub >> 2)) * 8 + g;
    int k = ks * 16 + ((sub >> 1) & 1) * 8 + 2 * tig + (sub & 1);
    const float* W; int k0;
    if (ci < 4)       { W = We1; k0 = ci * 64; }
    else if (ci < 6)  { W = We2; k0 = (ci - 4) * 64; }
    else if (ci < 8)  { W = Wc1; k0 = (ci - 6) * 64; }
    else if (ci < 12) { W = Wn1; k0 = (ci - 8) * 64; }
    else              { W = Wn2; k0 = (ci - 12) * 64; }
    g_wimg16[ci * 8192 + rec * 256 + slot_of(lane) * 8 + sub] =
        __float2half(W[(k0 + k) * DD + n]);
}

// ---------------- mma cores: warp tile = 2 etiles x FULL 128 n ----------------
__device__ __forceinline__ void mma_l1(float (&C)[2][16][4], uint32_t xa0, uint32_t xa1,
                                       uint32_t wimg_u, uint32_t slot16) {
#pragma unroll
    for (int ks = 0; ks < 4; ks++) {
        uint4 a0 = lds128(xa0 + (uint32_t)(ks << 9) + slot16);
        uint4 a1 = lds128(xa1 + (uint32_t)(ks << 9) + slot16);
#pragma unroll
        for (int ntp = 0; ntp < 8; ntp++) {
            uint4 b = lds128(wimg_u + (uint32_t)(((ntp * 4 + ks) << 9)) + slot16);
            mma16(C[0][2 * ntp],     a0, b.x, b.y);
            mma16(C[0][2 * ntp + 1], a0, b.z, b.w);
            mma16(C[1][2 * ntp],     a1, b.x, b.y);
            mma16(C[1][2 * ntp + 1], a1, b.z, b.w);
        }
    }
}

__device__ __forceinline__ void mma_reg(float (&C)[2][16][4], uint4 (&A)[2][8],
                                        uint32_t wb0, uint32_t slot16) {
#pragma unroll
    for (int ks = 0; ks < 8; ks++) {
        uint32_t wimg = wb0 + (uint32_t)((ks >> 2) * 16384);
        int ksl = ks & 3;
#pragma unroll
        for (int ntp = 0; ntp < 8; ntp++) {
            uint4 b = lds128(wimg + (uint32_t)(((ntp * 4 + ksl) << 9)) + slot16);
            mma16(C[0][2 * ntp],     A[0][ks], b.x, b.y);
            mma16(C[0][2 * ntp + 1], A[0][ks], b.z, b.w);
            mma16(C[1][2 * ntp],     A[1][ks], b.x, b.y);
            mma16(C[1][2 * ntp + 1], A[1][ks], b.z, b.w);
        }
    }
}

__device__ __forceinline__ void stageW(uint32_t wbuf_u, const __half* __restrict__ img, int t) {
#pragma unroll
    for (int i = 0; i < 8; i++)
        CP_ASYNC_16(wbuf_u + (uint32_t)((i * 128 + t) * 16), (const char*)(img + (i * 128 + t) * 8));
}

__device__ __forceinline__ void gatherX(uint32_t xbuf_u, int c, int w, int g, int tig,
                                        uint32_t slot16, const __half* __restrict__ hb,
                                        const int* srow, const int* scol) {
#pragma unroll
    for (int mtl = 0; mtl < 2; mtl++) {
        int etile = 2 * w + mtl;
        int nlo = (c < 2 ? srow : scol)[etile * 16 + g];
        int nhi = (c < 2 ? srow : scol)[etile * 16 + g + 8];
        const __half* slo = hb + (long long)nlo * DD + (c & 1) * 64 + 2 * tig;
        const __half* shi = hb + (long long)nhi * DD + (c & 1) * 64 + 2 * tig;
#pragma unroll
        for (int ks = 0; ks < 4; ks++) {
            uint32_t rec = xbuf_u + (uint32_t)(((etile * 4 + ks) << 9)) + slot16;
            CP_ASYNC_4(rec + 0,  (const char*)(slo + ks * 16));
            CP_ASYNC_4(rec + 4,  (const char*)(shi + ks * 16));
            CP_ASYNC_4(rec + 8,  (const char*)(slo + ks * 16 + 8));
            CP_ASYNC_4(rec + 12, (const char*)(shi + ks * 16 + 8));
        }
    }
}

__device__ __forceinline__ void gatherN(uint32_t xbuf_u, const __half* __restrict__ hb,
                                        long long n0, long long Nn, int w, int g, int tig,
                                        uint32_t slot16) {
#pragma unroll
    for (int mtl = 0; mtl < 2; mtl++) {
        int etile = 2 * w + mtl;
        long long rlo = n0 + etile * 16 + g;     if (rlo >= Nn) rlo = Nn - 1;
        long long rhi = n0 + etile * 16 + g + 8; if (rhi >= Nn) rhi = Nn - 1;
        const __half* slo = hb + rlo * DD + 2 * tig;
        const __half* shi = hb + rhi * DD + 2 * tig;
#pragma unroll
        for (int ks = 0; ks < 4; ks++) {
            uint32_t rec = xbuf_u + (uint32_t)(((etile * 4 + ks) << 9)) + slot16;
            CP_ASYNC_4(rec + 0,  (const char*)(slo + ks * 16));
            CP_ASYNC_4(rec + 4,  (const char*)(shi + ks * 16));
            CP_ASYNC_4(rec + 8,  (const char*)(slo + ks * 16 + 8));
            CP_ASYNC_4(rec + 12, (const char*)(shi + ks * 16 + 8));
        }
    }
}

#define CLEAR_C() \
    _Pragma("unroll") for (int mt = 0; mt < 2; mt++) \
    _Pragma("unroll") for (int nt = 0; nt < 16; nt++) \
    _Pragma("unroll") for (int q = 0; q < 4; q++) C[mt][nt][q] = 0.0f

// ================= edge kernel =================
__global__ __launch_bounds__(128, 2) void egnn_edge_mma(
    const float* __restrict__ pos, const int* __restrict__ ei32, long long E,
    const float* __restrict__ We1, const float* __restrict__ be1,
    const float* __restrict__ be2, const float* __restrict__ bc1,
    const float* __restrict__ Wc2, float* __restrict__ pos_out)
{
    extern __shared__ __align__(16) float smem[];
    char* sb = (char*)smem;
    const uint32_t sbase = smem_u32(smem);
    int*   srow  = (int*)(sb + SROW_B);
    int*   scol  = (int*)(sb + SCOL_B);
    float* sdx   = (float*)(sb + SDX_B);
    float* sdy   = (float*)(sb + SDY_B);
    float* sdz   = (float*)(sb + SDZ_B);
    float* sid   = (float*)(sb + SID_B);
    float* sdist = (float*)(sb + SDIST_B);
    float* w257s = (float*)(sb + W257_B);
    float* swc2  = (float*)(sb + SWC2_B);
    float* sbe1  = (float*)(sb + SBE1_B);
    float* sbe2  = (float*)(sb + SBE2_B);
    float* sbc1  = (float*)(sb + SBC1_B);

    const int t = threadIdx.x;
    const int w = t >> 5;
    const int lane = t & 31;
    const int g = lane >> 2;
    const int tig = lane & 3;
    const int e0t = 2 * w;
    const uint32_t slot16 = (uint32_t)(slot_of(lane) * 16);
    const long long e0 = (long long)blockIdx.x * EPB;

    {   // edge meta + tables (one edge per thread)
        long long e = e0 + t;
        if (e >= E) e = E - 1;
        int r, c;
        if (g_is64) { r = ei32[2 * e]; c = ei32[2 * (E + e)]; }
        else        { r = ei32[e];     c = ei32[E + e]; }
        srow[t] = r; scol[t] = c;
        float dx = pos[r * 3 + 0] - pos[c * 3 + 0];
        float dy = pos[r * 3 + 1] - pos[c * 3 + 1];
        float dz = pos[r * 3 + 2] - pos[c * 3 + 2];
        float d = sqrtf(dx * dx + dy * dy + dz * dz);
        d = fmaxf(d, 1e-6f);
        sdx[t] = dx; sdy[t] = dy; sdz[t] = dz;
        sid[t] = 1.0f / d; sdist[t] = d;
        w257s[t] = We1[256 * DD + t];
        swc2[t]  = Wc2[t];
        sbe1[t]  = be1[t];
        sbe2[t]  = be2[t];
        sbc1[t]  = bc1[t];
    }
    __syncthreads();

    float C[2][16][4];
    uint4 Af[2][8];          // next-layer A fragments; msg stays here through layer 3
    const uint32_t xb0 = sbase + XB_B;
    const uint32_t wb0 = sbase + WB_B;

    // ---------- layer 1: K=256, 4 pipelined K=64 chunks ----------
    CLEAR_C();
    stageW(wb0, g_wimg16 + 0 * 8192, t);
    gatherX(xb0, 0, w, g, tig, slot16, g_h16, srow, scol);
    CP_COMMIT();
    stageW(wb0 + 16384, g_wimg16 + 1 * 8192, t);
    gatherX(xb0 + 16384, 1, w, g, tig, slot16, g_h16, srow, scol);
    CP_COMMIT();

#pragma unroll
    for (int c = 0; c < 4; c++) {
        if (c < 3) CP_WAIT(1); else CP_WAIT(0);
        __syncthreads();
        uint32_t bx = xb0 + (uint32_t)((c & 1) * 16384);
        mma_l1(C, bx + (uint32_t)((e0t * 4) << 9), bx + (uint32_t)(((e0t + 1) * 4) << 9),
               wb0 + (uint32_t)((c & 1) * 16384), slot16);
        __syncthreads();
        if (c < 2) {
            stageW(wb0 + (uint32_t)((c & 1) * 16384), g_wimg16 + (c + 2) * 8192, t);
            gatherX(xb0 + (uint32_t)((c & 1) * 16384), c + 2, w, g, tig, slot16,
                    g_h16, srow, scol);
            CP_COMMIT();
        }
    }

    stageW(wb0, g_wimg16 + 4 * 8192, t);
    stageW(wb0 + 16384, g_wimg16 + 5 * 8192, t);
    CP_COMMIT();

    // epilogue 1: + dist*w257 + be1, silu -> Af (registers only)
#pragma unroll
    for (int mt = 0; mt < 2; mt++) {
        int etile = e0t + mt;
        float dlo = sdist[etile * 16 + g];
        float dhi = sdist[etile * 16 + g + 8];
#pragma unroll
        for (int l = 0; l < 8; l++) {
            int nt0 = 2 * l, nt1 = nt0 + 1;
            int n00 = nt0 * 8 + 2 * tig, n01 = n00 + 1;
            int n10 = nt1 * 8 + 2 * tig, n11 = n10 + 1;
            float w00 = w257s[n00], w01 = w257s[n01], w10 = w257s[n10], w11 = w257s[n11];
            float b00 = sbe1[n00], b01 = sbe1[n01], b10 = sbe1[n10], b11 = sbe1[n11];
            uint4 v;
            v.x = h2u(silu_f(C[mt][nt0][0] + dlo * w00 + b00), silu_f(C[mt][nt0][1] + dlo * w01 + b01));
            v.y = h2u(silu_f(C[mt][nt0][2] + dhi * w00 + b00), silu_f(C[mt][nt0][3] + dhi * w01 + b01));
            v.z = h2u(silu_f(C[mt][nt1][0] + dlo * w10 + b10), silu_f(C[mt][nt1][1] + dlo * w11 + b11));
            v.w = h2u(silu_f(C[mt][nt1][2] + dhi * w10 + b10), silu_f(C[mt][nt1][3] + dhi * w11 + b11));
            Af[mt][l] = v;
        }
    }
    CP_WAIT(0);
    __syncthreads();   // layer-2 weights visible

    // ---------- layer 2: K=128, A register-resident ----------
    CLEAR_C();
    mma_reg(C, Af, wb0, slot16);
    __syncthreads();   // all warps done reading layer-2 W

    stageW(wb0, g_wimg16 + 6 * 8192, t);
    stageW(wb0 + 16384, g_wimg16 + 7 * 8192, t);
    CP_COMMIT();

    // epilogue 2: msg = silu(C + be2) -> Af (registers only; no smem)
#pragma unroll
    for (int mt = 0; mt < 2; mt++) {
#pragma unroll
        for (int l = 0; l < 8; l++) {
            int nt0 = 2 * l, nt1 = nt0 + 1;
            int n00 = nt0 * 8 + 2 * tig, n01 = n00 + 1;
            int n10 = nt1 * 8 + 2 * tig, n11 = n10 + 1;
            float b00 = sbe2[n00], b01 = sbe2[n01], b10 = sbe2[n10], b11 = sbe2[n11];
            uint4 v;
            v.x = h2u(silu_f(C[mt][nt0][0] + b00), silu_f(C[mt][nt0][1] + b01));
            v.y = h2u(silu_f(C[mt][nt0][2] + b00), silu_f(C[mt][nt0][3] + b01));
            v.z = h2u(silu_f(C[mt][nt1][0] + b10), silu_f(C[mt][nt1][1] + b11));
            v.w = h2u(silu_f(C[mt][nt1][2] + b10), silu_f(C[mt][nt1][3] + b11));
            Af[mt][l] = v;
        }
    }
    CP_WAIT(0);
    __syncthreads();   // layer-3 weights visible

    // ---------- layer 3: K=128, A register-resident ----------
    CLEAR_C();
    mma_reg(C, Af, wb0, slot16);

    // agg scatter DIRECTLY from Af registers (msg); no smem round-trip
    if (e0 + EPB <= E) {
#pragma unroll
        for (int mt = 0; mt < 2; mt++) {
            float* plo = g_agg + (long long)srow[(e0t + mt) * 16 + g] * DD + 2 * tig;
            float* phi = g_agg + (long long)srow[(e0t + mt) * 16 + g + 8] * DD + 2 * tig;
#pragma unroll
            for (int l = 0; l < 8; l++) {
                float2 fx = u2f2(Af[mt][l].x);
                float2 fy = u2f2(Af[mt][l].y);
                float2 fz = u2f2(Af[mt][l].z);
                float2 fw = u2f2(Af[mt][l].w);
                atomicAdd(plo + 16 * l,     fx.x);
                atomicAdd(plo + 16 * l + 1, fx.y);
                atomicAdd(phi + 16 * l,     fy.x);
                atomicAdd(phi + 16 * l + 1, fy.y);
                atomicAdd(plo + 16 * l + 8, fz.x);
                atomicAdd(plo + 16 * l + 9, fz.y);
                atomicAdd(phi + 16 * l + 8, fw.x);
                atomicAdd(phi + 16 * l + 9, fw.y);
            }
        }
    } else {
#pragma unroll
        for (int mt = 0; mt < 2; mt++) {
            bool oklo = e0 + (e0t + mt) * 16 + g < E;
            bool okhi = e0 + (e0t + mt) * 16 + g + 8 < E;
            float* plo = g_agg + (long long)srow[(e0t + mt) * 16 + g] * DD + 2 * tig;
            float* phi = g_agg + (long long)srow[(e0t + mt) * 16 + g + 8] * DD + 2 * tig;
#pragma unroll
            for (int l = 0; l < 8; l++) {
                float2 fx = u2f2(Af[mt][l].x);
                float2 fy = u2f2(Af[mt][l].y);
                float2 fz = u2f2(Af[mt][l].z);
                float2 fw = u2f2(Af[mt][l].w);
                if (oklo) {
                    atomicAdd(plo + 16 * l,     fx.x);
                    atomicAdd(plo + 16 * l + 1, fx.y);
                    atomicAdd(plo + 16 * l + 8, fz.x);
                    atomicAdd(plo + 16 * l + 9, fz.y);
                }
                if (okhi) {
                    atomicAdd(phi + 16 * l,     fy.x);
                    atomicAdd(phi + 16 * l + 1, fy.y);
                    atomicAdd(phi + 16 * l + 8, fw.x);
                    atomicAdd(phi + 16 * l + 9, fw.y);
                }
            }
        }
    }

    // coord epilogue: warp-local reduce -> pos atomics
    {
        float sp[2][2] = {{0.f, 0.f}, {0.f, 0.f}};
#pragma unroll
        for (int mt = 0; mt < 2; mt++)
#pragma unroll
            for (int nt = 0; nt < 16; nt++)
#pragma unroll
                for (int q = 0; q < 4; q++) {
                    int n = nt * 8 + 2 * tig + (q & 1);
                    sp[mt][q >> 1] += silu_f(C[mt][nt][q] + sbc1[n]) * swc2[n];
                }
#pragma unroll
        for (int mt = 0; mt < 2; mt++)
#pragma unroll
            for (int hb = 0; hb < 2; hb++) {
                float s = sp[mt][hb];
                s += __shfl_xor_sync(0xFFFFFFFFu, s, 1);
                s += __shfl_xor_sync(0xFFFFFFFFu, s, 2);
                sp[mt][hb] = s;
            }
        if (tig == 0) {
#pragma unroll
            for (int mt = 0; mt < 2; mt++)
#pragma unroll
                for (int hb = 0; hb < 2; hb++) {
                    int ew = (e0t + mt) * 16 + g + 8 * hb;
                    if (e0 + ew < E) {
                        float s = fminf(fmaxf(sp[mt][hb], -1.0f), 1.0f);
                        float fac = s * sid[ew];
                        long long rr = srow[ew];
                        atomicAdd(&pos_out[rr * 3 + 0], sdx[ew] * fac);
                        atomicAdd(&pos_out[rr * 3 + 1], sdy[ew] * fac);
                        atomicAdd(&pos_out[rr * 3 + 2], sdz[ew] * fac);
                    }
                }
        }
    }
}

// ================= node kernel =================
__global__ __launch_bounds__(128, 2) void egnn_node_mma(
    const float* __restrict__ h,
    const float* __restrict__ bn1, const float* __restrict__ bn2,
    float* __restrict__ h_out, long long N)
{
    extern __shared__ __align__(16) float smem[];
    char* sb = (char*)smem;
    const uint32_t sbase = smem_u32(smem);
    float* sbn1 = (float*)(sb + NBN1_B);
    float* sbn2 = (float*)(sb + NBN2_B);

    const int t = threadIdx.x;
    const int w = t >> 5;
    const int lane = t & 31;
    const int g = lane >> 2;
    const int tig = lane & 3;
    const int e0t = 2 * w;
    const uint32_t slot16 = (uint32_t)(slot_of(lane) * 16);
    const long long n0 = (long long)blockIdx.x * EPB;

    sbn1[t] = bn1[t];
    sbn2[t] = bn2[t];
    __syncthreads();

    float C[2][16][4];
    uint4 Af[2][8];
    const uint32_t xb0 = sbase + XB_B;
    const uint32_t wb0 = sbase + NWB_B;

    // layer A: K=256 ([h16 ; agg16]), 4 pipelined chunks
    CLEAR_C();
    stageW(wb0, g_wimg16 + 8 * 8192, t);
    gatherN(xb0, g_h16, n0, N, w, g, tig, slot16);
    CP_COMMIT();
    stageW(wb0 + 16384, g_wimg16 + 9 * 8192, t);
    gatherN(xb0 + 16384, g_h16 + 64, n0, N, w, g, tig, slot16);
    CP_COMMIT();

#pragma unroll
    for (int c = 0; c < 4; c++) {
        if (c < 3) CP_WAIT(1); else CP_WAIT(0);
        __syncthreads();
        uint32_t bx = xb0 + (uint32_t)((c & 1) * 16384);
        mma_l1(C, bx + (uint32_t)((e0t * 4) << 9), bx + (uint32_t)(((e0t + 1) * 4) << 9),
               wb0 + (uint32_t)((c & 1) * 16384), slot16);
        __syncthreads();
        if (c < 2) {
            const __half* base = g_agg16 + (c & 1) * 64;
            stageW(wb0 + (uint32_t)((c & 1) * 16384), g_wimg16 + (10 + c) * 8192, t);
            gatherN(xb0 + (uint32_t)((c & 1) * 16384), base, n0, N, w, g, tig, slot16);
            CP_COMMIT();
        }
    }

    stageW(wb0, g_wimg16 + 12 * 8192, t);
    stageW(wb0 + 16384, g_wimg16 + 13 * 8192, t);
    CP_COMMIT();

    // epilogue A: silu(C + bn1) -> Af (registers only)
#pragma unroll
    for (int mt = 0; mt < 2; mt++) {
#pragma unroll
        for (int l = 0; l < 8; l++) {
            int nt0 = 2 * l, nt1 = nt0 + 1;
            int n00 = nt0 * 8 + 2 * tig, n01 = n00 + 1;
            int n10 = nt1 * 8 + 2 * tig, n11 = n10 + 1;
            float b00 = sbn1[n00], b01 = sbn1[n01], b10 = sbn1[n10], b11 = sbn1[n11];
            uint4 v;
            v.x = h2u(silu_f(C[mt][nt0][0] + b00), silu_f(C[mt][nt0][1] + b01));
            v.y = h2u(silu_f(C[mt][nt0][2] + b00), silu_f(C[mt][nt0][3] + b01));
            v.z = h2u(silu_f(C[mt][nt1][0] + b10), silu_f(C[mt][nt1][1] + b11));
            v.w = h2u(silu_f(C[mt][nt1][2] + b10), silu_f(C[mt][nt1][3] + b11));
            Af[mt][l] = v;
        }
    }
    CP_WAIT(0);
    __syncthreads();

    // layer B: K=128, A register-resident
    CLEAR_C();
    mma_reg(C, Af, wb0, slot16);

    // epilogue B: h_out = h + C + bn2 (direct float2 gmem)
#pragma unroll
    for (int mt = 0; mt < 2; mt++) {
        int etile = e0t + mt;
#pragma unroll
        for (int nt = 0; nt < 16; nt++) {
            int n = nt * 8 + 2 * tig;
            float b0 = sbn2[n], b1 = sbn2[n + 1];
#pragma unroll
            for (int qh = 0; qh < 2; qh++) {
                long long node = n0 + etile * 16 + g + 8 * qh;
                if (node < N) {
                    float2 hv = *reinterpret_cast<const float2*>(h + node * DD + n);
                    float2 o;
                    o.x = hv.x + C[mt][nt][2 * qh + 0] + b0;
                    o.y = hv.y + C[mt][nt][2 * qh + 1] + b1;
                    *reinterpret_cast<float2*>(h_out + node * DD + n) = o;
                }
            }
        }
    }
}

// ---------------- launcher ----------------
extern "C" void kernel_launch(void* const* d_in, const int* in_sizes, int n_in,
                              void* d_out, int out_size)
{
    const float* h   = (const float*)d_in[0];
    const float* pos = (const float*)d_in[1];
    const int*   ei  = (const int*)d_in[2];
    const float* We1 = (const float*)d_in[3];
    const float* be1 = (const float*)d_in[4];
    const float* We2 = (const float*)d_in[5];
    const float* be2 = (const float*)d_in[6];
    const float* Wn1 = (const float*)d_in[7];
    const float* bn1 = (const float*)d_in[8];
    const float* Wn2 = (const float*)d_in[9];
    const float* bn2 = (const float*)d_in[10];
    const float* Wc1 = (const float*)d_in[11];
    const float* bc1 = (const float*)d_in[12];
    const float* Wc2 = (const float*)d_in[13];

    const long long N = in_sizes[0] / DD;
    const long long E = (long long)in_sizes[2] / 2;

    float* h_out   = (float*)d_out;
    float* pos_out = h_out + N * DD;

    cudaFuncSetAttribute(egnn_edge_mma, cudaFuncAttributeMaxDynamicSharedMemorySize, EDGE_SMEM_BYTES);
    cudaFuncSetAttribute(egnn_node_mma, cudaFuncAttributeMaxDynamicSharedMemorySize, NODE_SMEM_BYTES);

    egnn_detect_kernel<<<1, 1>>>(ei);
    egnn_prep_w<<<(14 * 8192 + 255) / 256, 256>>>(We1, We2, Wc1, Wn1, Wn2);

    long long nAgg = N * DD;
    long long nPos = N * 3;
    egnn_init_kernel<<<(int)((nAgg + 255) / 256), 256>>>(pos, h, pos_out, nAgg, nPos);

    int eb = (int)((E + EPB - 1) / EPB);
    egnn_edge_mma<<<eb, 128, EDGE_SMEM_BYTES>>>(
        pos, ei, E, We1, be1, be2, bc1, Wc2, pos_out);

    egnn_conv_agg<<<(int)((nAgg + 255) / 256), 256>>>(nAgg);

    int nb = (int)((N + EPB - 1) / EPB);
    egnn_node_mma<<<nb, 128, NODE_SMEM_BYTES>>>(
        h, bn1, bn2, h_out, N);
}

// round 16
// speedup vs baseline: 1.0410x; 1.0410x over previous
#include <cuda_runtime.h>
#include <cuda_fp16.h>
#include <cstdint>

#define DD 128
#define EPB 128        // edges (or nodes) per block; 128 threads / 4 warps

__device__ float  g_agg[50000 * 128];
__device__ __half g_h16[50000 * 128];
__device__ __half g_agg16[50000 * 128];
__device__ int    g_is64;
// 14 chunk images x 8192 halves (16KB): We1 0-3, We2 4-5, Wc1 6-7, Wn1 8-11, Wn2 12-13
__device__ __half g_wimg16[14 * 8192];

// ---------------- helpers ----------------
__device__ __forceinline__ uint32_t smem_u32(const void* p) {
    uint32_t a;
    asm("{ .reg .u64 t; cvta.to.shared.u64 t, %1; cvt.u32.u64 %0, t; }" : "=r"(a) : "l"(p));
    return a;
}
__device__ __forceinline__ float tanh_a(float x) {
    float y;
    asm("tanh.approx.f32 %0, %1;" : "=f"(y) : "f"(x));
    return y;
}
__device__ __forceinline__ float silu_f(float x) {
    float hx = 0.5f * x;
    return hx + hx * tanh_a(hx);
}
__device__ __forceinline__ int slot_of(int L) { return L ^ ((L >> 3) & 3); }

__device__ __forceinline__ uint4 lds128(uint32_t a) {
    uint4 v;
    asm volatile("ld.shared.v4.b32 {%0,%1,%2,%3}, [%4];"
                 : "=r"(v.x), "=r"(v.y), "=r"(v.z), "=r"(v.w) : "r"(a));
    return v;
}
__device__ __forceinline__ void sts128(uint32_t a, uint4 v) {
    asm volatile("st.shared.v4.b32 [%0], {%1,%2,%3,%4};"
                 :: "r"(a), "r"(v.x), "r"(v.y), "r"(v.z), "r"(v.w) : "memory");
}
__device__ __forceinline__ void mma16(float* c, uint4 a, uint32_t b0, uint32_t b1) {
    asm volatile(
        "mma.sync.aligned.m16n8k16.row.col.f32.f16.f16.f32 "
        "{%0,%1,%2,%3}, {%4,%5,%6,%7}, {%8,%9}, {%0,%1,%2,%3};"
        : "+f"(c[0]), "+f"(c[1]), "+f"(c[2]), "+f"(c[3])
        : "r"(a.x), "r"(a.y), "r"(a.z), "r"(a.w), "r"(b0), "r"(b1));
}
__device__ __forceinline__ uint32_t h2u(float lo, float hi) {
    __half2 h = __floats2half2_rn(lo, hi);
    return *reinterpret_cast<uint32_t*>(&h);
}
#define CP_ASYNC_4(dst, src) \
    asm volatile("cp.async.ca.shared.global [%0], [%1], 4;" :: "r"(dst), "l"(src) : "memory")
#define CP_ASYNC_16(dst, src) \
    asm volatile("cp.async.cg.shared.global [%0], [%1], 16;" :: "r"(dst), "l"(src) : "memory")
#define CP_COMMIT() asm volatile("cp.async.commit_group;" ::: "memory")
#define CP_WAIT(n)  asm volatile("cp.async.wait_group %0;" :: "n"(n) : "memory")

// ---------------- smem maps (bytes) ----------------
// XB: two 16KB K=64 layer-1 chunk slots (later X3 full layout).
// WB: FOUR 16KB weight slots: L1 ring = slots 0,1 (reused by L3); L2 = slots 2,3.
#define XB_B    0
#define WB_B    32768
#define SROW_B  98304
#define SCOL_B  98816
#define SDX_B   99328
#define SDY_B   99840
#define SDZ_B   100352
#define SID_B   100864
#define SDIST_B 101376
#define W257_B  101888
#define SWC2_B  102400
#define SBE1_B  102912
#define SBE2_B  103424
#define SBC1_B  103936
#define EDGE_SMEM_BYTES 104448

#define NWB_B   32768
#define NBN1_B  98304
#define NBN2_B  98816
#define NODE_SMEM_BYTES 99328

// ---------------- small kernels ----------------
__global__ void egnn_detect_kernel(const int* __restrict__ ei32) {
    int is64 = 1;
#pragma unroll
    for (int i = 1; i < 64; i += 2)
        if (ei32[i] != 0) is64 = 0;
    g_is64 = is64;
}

__global__ void egnn_init_kernel(const float* __restrict__ pos, const float* __restrict__ h,
                                 float* __restrict__ pos_out,
                                 long long nAgg, long long nPos) {
    long long i = (long long)blockIdx.x * blockDim.x + threadIdx.x;
    if (i < nAgg) { g_agg[i] = 0.0f; g_h16[i] = __float2half(h[i]); }
    if (i < nPos) pos_out[i] = pos[i];
}

__global__ void egnn_conv_agg(long long nAgg) {
    long long i = (long long)blockIdx.x * blockDim.x + threadIdx.x;
    if (i < nAgg) g_agg16[i] = __float2half(g_agg[i]);
}

// fp16 B-fragment chunk images (identical encoding to R9-R15 — proven).
__global__ void egnn_prep_w(const float* __restrict__ We1, const float* __restrict__ We2,
                            const float* __restrict__ Wc1, const float* __restrict__ Wn1,
                            const float* __restrict__ Wn2) {
    int i = blockIdx.x * 256 + threadIdx.x;
    if (i >= 14 * 8192) return;
    int ci = i >> 13;
    int r = i & 8191;
    int rec = r >> 8;
    int lane = (r >> 3) & 31;
    int sub = r & 7;
    int ntp = rec >> 2, ks = rec & 3;
    int g = lane >> 2, tig = lane & 3;
    int n = (ntp * 2 + (sub >> 2)) * 8 + g;
    int k = ks * 16 + ((sub >> 1) & 1) * 8 + 2 * tig + (sub & 1);
    const float* W; int k0;
    if (ci < 4)       { W = We1; k0 = ci * 64; }
    else if (ci < 6)  { W = We2; k0 = (ci - 4) * 64; }
    else if (ci < 8)  { W = Wc1; k0 = (ci - 6) * 64; }
    else if (ci < 12) { W = Wn1; k0 = (ci - 8) * 64; }
    else              { W = Wn2; k0 = (ci - 12) * 64; }
    g_wimg16[ci * 8192 + rec * 256 + slot_of(lane) * 8 + sub] =
        __float2half(W[(k0 + k) * DD + n]);
}

// ---------------- mma cores: warp tile = 2 etiles x FULL 128 n ----------------
__device__ __forceinline__ void mma_l1(float (&C)[2][16][4], uint32_t xa0, uint32_t xa1,
                                       uint32_t wimg_u, uint32_t slot16) {
#pragma unroll
    for (int ks = 0; ks < 4; ks++) {
        uint4 a0 = lds128(xa0 + (uint32_t)(ks << 9) + slot16);
        uint4 a1 = lds128(xa1 + (uint32_t)(ks << 9) + slot16);
#pragma unroll
        for (int ntp = 0; ntp < 8; ntp++) {
            uint4 b = lds128(wimg_u + (uint32_t)(((ntp * 4 + ks) << 9)) + slot16);
            mma16(C[0][2 * ntp],     a0, b.x, b.y);
            mma16(C[0][2 * ntp + 1], a0, b.z, b.w);
            mma16(C[1][2 * ntp],     a1, b.x, b.y);
            mma16(C[1][2 * ntp + 1], a1, b.z, b.w);
        }
    }
}

__device__ __forceinline__ void mma_reg(float (&C)[2][16][4], uint4 (&A)[2][8],
                                        uint32_t wbase, uint32_t slot16) {
#pragma unroll
    for (int ks = 0; ks < 8; ks++) {
        uint32_t wimg = wbase + (uint32_t)((ks >> 2) * 16384);
        int ksl = ks & 3;
#pragma unroll
        for (int ntp = 0; ntp < 8; ntp++) {
            uint4 b = lds128(wimg + (uint32_t)(((ntp * 4 + ksl) << 9)) + slot16);
            mma16(C[0][2 * ntp],     A[0][ks], b.x, b.y);
            mma16(C[0][2 * ntp + 1], A[0][ks], b.z, b.w);
            mma16(C[1][2 * ntp],     A[1][ks], b.x, b.y);
            mma16(C[1][2 * ntp + 1], A[1][ks], b.z, b.w);
        }
    }
}

__device__ __forceinline__ void stageW(uint32_t wbuf_u, const __half* __restrict__ img, int t) {
#pragma unroll
    for (int i = 0; i < 8; i++)
        CP_ASYNC_16(wbuf_u + (uint32_t)((i * 128 + t) * 16), (const char*)(img + (i * 128 + t) * 8));
}

__device__ __forceinline__ void gatherX(uint32_t xbuf_u, int c, int w, int g, int tig,
                                        uint32_t slot16, const __half* __restrict__ hb,
                                        const int* srow, const int* scol) {
#pragma unroll
    for (int mtl = 0; mtl < 2; mtl++) {
        int etile = 2 * w + mtl;
        int nlo = (c < 2 ? srow : scol)[etile * 16 + g];
        int nhi = (c < 2 ? srow : scol)[etile * 16 + g + 8];
        const __half* slo = hb + (long long)nlo * DD + (c & 1) * 64 + 2 * tig;
        const __half* shi = hb + (long long)nhi * DD + (c & 1) * 64 + 2 * tig;
#pragma unroll
        for (int ks = 0; ks < 4; ks++) {
            uint32_t rec = xbuf_u + (uint32_t)(((etile * 4 + ks) << 9)) + slot16;
            CP_ASYNC_4(rec + 0,  (const char*)(slo + ks * 16));
            CP_ASYNC_4(rec + 4,  (const char*)(shi + ks * 16));
            CP_ASYNC_4(rec + 8,  (const char*)(slo + ks * 16 + 8));
            CP_ASYNC_4(rec + 12, (const char*)(shi + ks * 16 + 8));
        }
    }
}

__device__ __forceinline__ void gatherN(uint32_t xbuf_u, const __half* __restrict__ hb,
                                        long long n0, long long Nn, int w, int g, int tig,
                                        uint32_t slot16) {
#pragma unroll
    for (int mtl = 0; mtl < 2; mtl++) {
        int etile = 2 * w + mtl;
        long long rlo = n0 + etile * 16 + g;     if (rlo >= Nn) rlo = Nn - 1;
        long long rhi = n0 + etile * 16 + g + 8; if (rhi >= Nn) rhi = Nn - 1;
        const __half* slo = hb + rlo * DD + 2 * tig;
        const __half* shi = hb + rhi * DD + 2 * tig;
#pragma unroll
        for (int ks = 0; ks < 4; ks++) {
            uint32_t rec = xbuf_u + (uint32_t)(((etile * 4 + ks) << 9)) + slot16;
            CP_ASYNC_4(rec + 0,  (const char*)(slo + ks * 16));
            CP_ASYNC_4(rec + 4,  (const char*)(shi + ks * 16));
            CP_ASYNC_4(rec + 8,  (const char*)(slo + ks * 16 + 8));
            CP_ASYNC_4(rec + 12, (const char*)(shi + ks * 16 + 8));
        }
    }
}

#define CLEAR_C() \
    _Pragma("unroll") for (int mt = 0; mt < 2; mt++) \
    _Pragma("unroll") for (int nt = 0; nt < 16; nt++) \
    _Pragma("unroll") for (int q = 0; q < 4; q++) C[mt][nt][q] = 0.0f

// ================= edge kernel =================
__global__ __launch_bounds__(128, 2) void egnn_edge_mma(
    const float* __restrict__ pos, const int* __restrict__ ei32, long long E,
    const float* __restrict__ We1, const float* __restrict__ be1,
    const float* __restrict__ be2, const float* __restrict__ bc1,
    const float* __restrict__ Wc2, float* __restrict__ pos_out)
{
    extern __shared__ __align__(16) float smem[];
    char* sb = (char*)smem;
    const uint32_t sbase = smem_u32(smem);
    __half* xh   = (__half*)(sb + XB_B);
    int*   srow  = (int*)(sb + SROW_B);
    int*   scol  = (int*)(sb + SCOL_B);
    float* sdx   = (float*)(sb + SDX_B);
    float* sdy   = (float*)(sb + SDY_B);
    float* sdz   = (float*)(sb + SDZ_B);
    float* sid   = (float*)(sb + SID_B);
    float* sdist = (float*)(sb + SDIST_B);
    float* w257s = (float*)(sb + W257_B);
    float* swc2  = (float*)(sb + SWC2_B);
    float* sbe1  = (float*)(sb + SBE1_B);
    float* sbe2  = (float*)(sb + SBE2_B);
    float* sbc1  = (float*)(sb + SBC1_B);

    const int t = threadIdx.x;
    const int w = t >> 5;
    const int lane = t & 31;
    const int g = lane >> 2;
    const int tig = lane & 3;
    const int e0t = 2 * w;
    const uint32_t slot16 = (uint32_t)(slot_of(lane) * 16);
    const long long e0 = (long long)blockIdx.x * EPB;

    {   // edge meta + tables (one edge per thread)
        long long e = e0 + t;
        if (e >= E) e = E - 1;
        int r, c;
        if (g_is64) { r = ei32[2 * e]; c = ei32[2 * (E + e)]; }
        else        { r = ei32[e];     c = ei32[E + e]; }
        srow[t] = r; scol[t] = c;
        float dx = pos[r * 3 + 0] - pos[c * 3 + 0];
        float dy = pos[r * 3 + 1] - pos[c * 3 + 1];
        float dz = pos[r * 3 + 2] - pos[c * 3 + 2];
        float d = sqrtf(dx * dx + dy * dy + dz * dz);
        d = fmaxf(d, 1e-6f);
        sdx[t] = dx; sdy[t] = dy; sdz[t] = dz;
        sid[t] = 1.0f / d; sdist[t] = d;
        w257s[t] = We1[256 * DD + t];
        swc2[t]  = Wc2[t];
        sbe1[t]  = be1[t];
        sbe2[t]  = be2[t];
        sbc1[t]  = bc1[t];
    }
    __syncthreads();

    float C[2][16][4];
    uint4 Af[2][8];
    const uint32_t xb0 = sbase + XB_B;
    const uint32_t wb0 = sbase + WB_B;

    // ---------- layer 1: K=256, 4 pipelined K=64 chunks ----------
    // G0 also carries BOTH layer-2 weight images (slots 2,3) — free during layer 1.
    CLEAR_C();
    stageW(wb0 + 2 * 16384, g_wimg16 + 4 * 8192, t);
    stageW(wb0 + 3 * 16384, g_wimg16 + 5 * 8192, t);
    stageW(wb0, g_wimg16 + 0 * 8192, t);
    gatherX(xb0, 0, w, g, tig, slot16, g_h16, srow, scol);
    CP_COMMIT();                                                // G0
    stageW(wb0 + 16384, g_wimg16 + 1 * 8192, t);
    gatherX(xb0 + 16384, 1, w, g, tig, slot16, g_h16, srow, scol);
    CP_COMMIT();                                                // G1

#pragma unroll
    for (int c = 0; c < 4; c++) {
        if (c < 3) CP_WAIT(1); else CP_WAIT(0);
        __syncthreads();
        uint32_t bx = xb0 + (uint32_t)((c & 1) * 16384);
        mma_l1(C, bx + (uint32_t)((e0t * 4) << 9), bx + (uint32_t)(((e0t + 1) * 4) << 9),
               wb0 + (uint32_t)((c & 1) * 16384), slot16);
        __syncthreads();
        if (c < 2) {
            stageW(wb0 + (uint32_t)((c & 1) * 16384), g_wimg16 + (c + 2) * 8192, t);
            gatherX(xb0 + (uint32_t)((c & 1) * 16384), c + 2, w, g, tig, slot16,
                    g_h16, srow, scol);
            CP_COMMIT();
        }
    }

    // stage layer-3 weights into slots 0,1 (drains during epilogue 1 + layer 2)
    stageW(wb0, g_wimg16 + 6 * 8192, t);
    stageW(wb0 + 16384, g_wimg16 + 7 * 8192, t);
    CP_COMMIT();

    // epilogue 1: + dist*w257 + be1, silu -> Af (registers only)
#pragma unroll
    for (int mt = 0; mt < 2; mt++) {
        int etile = e0t + mt;
        float dlo = sdist[etile * 16 + g];
        float dhi = sdist[etile * 16 + g + 8];
#pragma unroll
        for (int l = 0; l < 8; l++) {
            int nt0 = 2 * l, nt1 = nt0 + 1;
            int n00 = nt0 * 8 + 2 * tig, n01 = n00 + 1;
            int n10 = nt1 * 8 + 2 * tig, n11 = n10 + 1;
            float w00 = w257s[n00], w01 = w257s[n01], w10 = w257s[n10], w11 = w257s[n11];
            float b00 = sbe1[n00], b01 = sbe1[n01], b10 = sbe1[n10], b11 = sbe1[n11];
            uint4 v;
            v.x = h2u(silu_f(C[mt][nt0][0] + dlo * w00 + b00), silu_f(C[mt][nt0][1] + dlo * w01 + b01));
            v.y = h2u(silu_f(C[mt][nt0][2] + dhi * w00 + b00), silu_f(C[mt][nt0][3] + dhi * w01 + b01));
            v.z = h2u(silu_f(C[mt][nt1][0] + dlo * w10 + b10), silu_f(C[mt][nt1][1] + dlo * w11 + b11));
            v.w = h2u(silu_f(C[mt][nt1][2] + dhi * w10 + b10), silu_f(C[mt][nt1][3] + dhi * w11 + b11));
            Af[mt][l] = v;
        }
    }

    // ---------- layer 2: K=128, A in registers, W already resident (slots 2,3) ----------
    CLEAR_C();
    mma_reg(C, Af, wb0 + 2 * 16384, slot16);

    // epilogue 2: msg = silu(C + be2) -> Af (regs) + X3 smem for the coalesced scatter
#pragma unroll
    for (int mt = 0; mt < 2; mt++) {
        int etile = e0t + mt;
#pragma unroll
        for (int l = 0; l < 8; l++) {
            int nt0 = 2 * l, nt1 = nt0 + 1;
            int n00 = nt0 * 8 + 2 * tig, n01 = n00 + 1;
            int n10 = nt1 * 8 + 2 * tig, n11 = n10 + 1;
            float b00 = sbe2[n00], b01 = sbe2[n01], b10 = sbe2[n10], b11 = sbe2[n11];
            uint4 v;
            v.x = h2u(silu_f(C[mt][nt0][0] + b00), silu_f(C[mt][nt0][1] + b01));
            v.y = h2u(silu_f(C[mt][nt0][2] + b00), silu_f(C[mt][nt0][3] + b01));
            v.z = h2u(silu_f(C[mt][nt1][0] + b10), silu_f(C[mt][nt1][1] + b11));
            v.w = h2u(silu_f(C[mt][nt1][2] + b10), silu_f(C[mt][nt1][3] + b11));
            Af[mt][l] = v;
            sts128(xb0 + (uint32_t)(((etile * 8 + l) << 9)) + slot16, v);
        }
    }
    CP_WAIT(0);
    __syncthreads();   // layer-3 weights + X3 visible

    // ---------- layer 3: K=128, A register-resident (slots 0,1) ----------
    CLEAR_C();
    mma_reg(C, Af, wb0, slot16);

    // agg scatter from X3 (R14-proven coalesced form)
    {
        int j = t;
        int ks2 = j >> 4, kcol = j & 15;
        int tigp = (kcol & 7) >> 1, jp = kcol & 1;
        int regp = (kcol >> 3) * 2;
        int offs[16];
#pragma unroll
        for (int r = 0; r < 16; r++) {
            int lanep = (r & 7) * 4 + tigp;
            offs[r] = ks2 * 256 + slot_of(lanep) * 8 + (regp + (r >> 3)) * 2 + jp;
        }
        float* aggj = g_agg + j;
        if (e0 + EPB <= E) {
#pragma unroll 2
            for (int eq = 0; eq < 8; eq++) {
                int base16 = eq * 2048;
                int ewb = eq * 16;
#pragma unroll
                for (int r = 0; r < 16; r++) {
                    float m = __half2float(xh[base16 + offs[r]]);
                    atomicAdd(aggj + (long long)srow[ewb + r] * DD, m);
                }
            }
        } else {
#pragma unroll 2
            for (int ew = 0; ew < 128; ew++) {
                if (e0 + ew < E) {
                    float m = __half2float(xh[(ew >> 4) * 2048 + offs[ew & 15]]);
                    atomicAdd(aggj + (long long)srow[ew] * DD, m);
                }
            }
        }
    }

    // coord epilogue: warp-local reduce -> pos atomics
    {
        float sp[2][2] = {{0.f, 0.f}, {0.f, 0.f}};
#pragma unroll
        for (int mt = 0; mt < 2; mt++)
#pragma unroll
            for (int nt = 0; nt < 16; nt++)
#pragma unroll
                for (int q = 0; q < 4; q++) {
                    int n = nt * 8 + 2 * tig + (q & 1);
                    sp[mt][q >> 1] += silu_f(C[mt][nt][q] + sbc1[n]) * swc2[n];
                }
#pragma unroll
        for (int mt = 0; mt < 2; mt++)
#pragma unroll
            for (int hb = 0; hb < 2; hb++) {
                float s = sp[mt][hb];
                s += __shfl_xor_sync(0xFFFFFFFFu, s, 1);
                s += __shfl_xor_sync(0xFFFFFFFFu, s, 2);
                sp[mt][hb] = s;
            }
        if (tig == 0) {
#pragma unroll
            for (int mt = 0; mt < 2; mt++)
#pragma unroll
                for (int hb = 0; hb < 2; hb++) {
                    int ew = (e0t + mt) * 16 + g + 8 * hb;
                    if (e0 + ew < E) {
                        float s = fminf(fmaxf(sp[mt][hb], -1.0f), 1.0f);
                        float fac = s * sid[ew];
                        long long rr = srow[ew];
                        atomicAdd(&pos_out[rr * 3 + 0], sdx[ew] * fac);
                        atomicAdd(&pos_out[rr * 3 + 1], sdy[ew] * fac);
                        atomicAdd(&pos_out[rr * 3 + 2], sdz[ew] * fac);
                    }
                }
        }
    }
}

// ================= node kernel =================
__global__ __launch_bounds__(128, 2) void egnn_node_mma(
    const float* __restrict__ h,
    const float* __restrict__ bn1, const float* __restrict__ bn2,
    float* __restrict__ h_out, long long N)
{
    extern __shared__ __align__(16) float smem[];
    char* sb = (char*)smem;
    const uint32_t sbase = smem_u32(smem);
    float* sbn1 = (float*)(sb + NBN1_B);
    float* sbn2 = (float*)(sb + NBN2_B);

    const int t = threadIdx.x;
    const int w = t >> 5;
    const int lane = t & 31;
    const int g = lane >> 2;
    const int tig = lane & 3;
    const int e0t = 2 * w;
    const uint32_t slot16 = (uint32_t)(slot_of(lane) * 16);
    const long long n0 = (long long)blockIdx.x * EPB;

    sbn1[t] = bn1[t];
    sbn2[t] = bn2[t];
    __syncthreads();

    float C[2][16][4];
    uint4 Af[2][8];
    const uint32_t xb0 = sbase + XB_B;
    const uint32_t wb0 = sbase + NWB_B;

    // layer A: K=256 ([h16 ; agg16]); layer-B weights ride in G0 (slots 2,3)
    CLEAR_C();
    stageW(wb0 + 2 * 16384, g_wimg16 + 12 * 8192, t);
    stageW(wb0 + 3 * 16384, g_wimg16 + 13 * 8192, t);
    stageW(wb0, g_wimg16 + 8 * 8192, t);
    gatherN(xb0, g_h16, n0, N, w, g, tig, slot16);
    CP_COMMIT();                                                // G0
    stageW(wb0 + 16384, g_wimg16 + 9 * 8192, t);
    gatherN(xb0 + 16384, g_h16 + 64, n0, N, w, g, tig, slot16);
    CP_COMMIT();                                                // G1

#pragma unroll
    for (int c = 0; c < 4; c++) {
        if (c < 3) CP_WAIT(1); else CP_WAIT(0);
        __syncthreads();
        uint32_t bx = xb0 + (uint32_t)((c & 1) * 16384);
        mma_l1(C, bx + (uint32_t)((e0t * 4) << 9), bx + (uint32_t)(((e0t + 1) * 4) << 9),
               wb0 + (uint32_t)((c & 1) * 16384), slot16);
        __syncthreads();
        if (c < 2) {
            const __half* base = g_agg16 + (c & 1) * 64;
            stageW(wb0 + (uint32_t)((c & 1) * 16384), g_wimg16 + (10 + c) * 8192, t);
            gatherN(xb0 + (uint32_t)((c & 1) * 16384), base, n0, N, w, g, tig, slot16);
            CP_COMMIT();
        }
    }

    // epilogue A: silu(C + bn1) -> Af (registers only)
#pragma unroll
    for (int mt = 0; mt < 2; mt++) {
#pragma unroll
        for (int l = 0; l < 8; l++) {
            int nt0 = 2 * l, nt1 = nt0 + 1;
            int n00 = nt0 * 8 + 2 * tig, n01 = n00 + 1;
            int n10 = nt1 * 8 + 2 * tig, n11 = n10 + 1;
            float b00 = sbn1[n00], b01 = sbn1[n01], b10 = sbn1[n10], b11 = sbn1[n11];
            uint4 v;
            v.x = h2u(silu_f(C[mt][nt0][0] + b00), silu_f(C[mt][nt0][1] + b01));
            v.y = h2u(silu_f(C[mt][nt0][2] + b00), silu_f(C[mt][nt0][3] + b01));
            v.z = h2u(silu_f(C[mt][nt1][0] + b10), silu_f(C[mt][nt1][1] + b11));
            v.w = h2u(silu_f(C[mt][nt1][2] + b10), silu_f(C[mt][nt1][3] + b11));
            Af[mt][l] = v;
        }
    }

    // layer B: K=128, W already resident in slots 2,3
    CLEAR_C();
    mma_reg(C, Af, wb0 + 2 * 16384, slot16);

    // epilogue B: h_out = h + C + bn2 (direct float2 gmem)
#pragma unroll
    for (int mt = 0; mt < 2; mt++) {
        int etile = e0t + mt;
#pragma unroll
        for (int nt = 0; nt < 16; nt++) {
            int n = nt * 8 + 2 * tig;
            float b0 = sbn2[n], b1 = sbn2[n + 1];
#pragma unroll
            for (int qh = 0; qh < 2; qh++) {
                long long node = n0 + etile * 16 + g + 8 * qh;
                if (node < N) {
                    float2 hv = *reinterpret_cast<const float2*>(h + node * DD + n);
                    float2 o;
                    o.x = hv.x + C[mt][nt][2 * qh + 0] + b0;
                    o.y = hv.y + C[mt][nt][2 * qh + 1] + b1;
                    *reinterpret_cast<float2*>(h_out + node * DD + n) = o;
                }
            }
        }
    }
}

// ---------------- launcher ----------------
extern "C" void kernel_launch(void* const* d_in, const int* in_sizes, int n_in,
                              void* d_out, int out_size)
{
    const float* h   = (const float*)d_in[0];
    const float* pos = (const float*)d_in[1];
    const int*   ei  = (const int*)d_in[2];
    const float* We1 = (const float*)d_in[3];
    const float* be1 = (const float*)d_in[4];
    const float* We2 = (const float*)d_in[5];
    const float* be2 = (const float*)d_in[6];
    const float* Wn1 = (const float*)d_in[7];
    const float* bn1 = (const float*)d_in[8];
    const float* Wn2 = (const float*)d_in[9];
    const float* bn2 = (const float*)d_in[10];
    const float* Wc1 = (const float*)d_in[11];
    const float* bc1 = (const float*)d_in[12];
    const float* Wc2 = (const float*)d_in[13];

    const long long N = in_sizes[0] / DD;
    const long long E = (long long)in_sizes[2] / 2;

    float* h_out   = (float*)d_out;
    float* pos_out = h_out + N * DD;

    cudaFuncSetAttribute(egnn_edge_mma, cudaFuncAttributeMaxDynamicSharedMemorySize, EDGE_SMEM_BYTES);
    cudaFuncSetAttribute(egnn_node_mma, cudaFuncAttributeMaxDynamicSharedMemorySize, NODE_SMEM_BYTES);

    egnn_detect_kernel<<<1, 1>>>(ei);
    egnn_prep_w<<<(14 * 8192 + 255) / 256, 256>>>(We1, We2, Wc1, Wn1, Wn2);

    long long nAgg = N * DD;
    long long nPos = N * 3;
    egnn_init_kernel<<<(int)((nAgg + 255) / 256), 256>>>(pos, h, pos_out, nAgg, nPos);

    int eb = (int)((E + EPB - 1) / EPB);
    egnn_edge_mma<<<eb, 128, EDGE_SMEM_BYTES>>>(
        pos, ei, E, We1, be1, be2, bc1, Wc2, pos_out);

    egnn_conv_agg<<<(int)((nAgg + 255) / 256), 256>>>(nAgg);

    int nb = (int)((N + EPB - 1) / EPB);
    egnn_node_mma<<<nb, 128, NODE_SMEM_BYTES>>>(
        h, bn1, bn2, h_out, N);
}

// round 17
// speedup vs baseline: 1.0624x; 1.0206x over previous
#include <cuda_runtime.h>
#include <cuda_fp16.h>
#include <cstdint>

#define DD 128
#define EPB 128        // edges (or nodes) per block; 128 threads / 4 warps

__device__ __half g_h16[50000 * 128];
__device__ __half g_agg16[50000 * 128];   // fp16 accumulation target (atomicAdd half2)
__device__ int    g_is64;
// 14 chunk images x 8192 halves (16KB): We1 0-3, We2 4-5, Wc1 6-7, Wn1 8-11, Wn2 12-13
__device__ __half g_wimg16[14 * 8192];

// ---------------- helpers ----------------
__device__ __forceinline__ uint32_t smem_u32(const void* p) {
    uint32_t a;
    asm("{ .reg .u64 t; cvta.to.shared.u64 t, %1; cvt.u32.u64 %0, t; }" : "=r"(a) : "l"(p));
    return a;
}
__device__ __forceinline__ float tanh_a(float x) {
    float y;
    asm("tanh.approx.f32 %0, %1;" : "=f"(y) : "f"(x));
    return y;
}
__device__ __forceinline__ float silu_f(float x) {
    float hx = 0.5f * x;
    return hx + hx * tanh_a(hx);
}
__device__ __forceinline__ int slot_of(int L) { return L ^ ((L >> 3) & 3); }

__device__ __forceinline__ uint4 lds128(uint32_t a) {
    uint4 v;
    asm volatile("ld.shared.v4.b32 {%0,%1,%2,%3}, [%4];"
                 : "=r"(v.x), "=r"(v.y), "=r"(v.z), "=r"(v.w) : "r"(a));
    return v;
}
__device__ __forceinline__ uint32_t lds32(uint32_t a) {
    uint32_t v;
    asm volatile("ld.shared.b32 %0, [%1];" : "=r"(v) : "r"(a));
    return v;
}
__device__ __forceinline__ void sts128(uint32_t a, uint4 v) {
    asm volatile("st.shared.v4.b32 [%0], {%1,%2,%3,%4};"
                 :: "r"(a), "r"(v.x), "r"(v.y), "r"(v.z), "r"(v.w) : "memory");
}
__device__ __forceinline__ void mma16(float* c, uint4 a, uint32_t b0, uint32_t b1) {
    asm volatile(
        "mma.sync.aligned.m16n8k16.row.col.f32.f16.f16.f32 "
        "{%0,%1,%2,%3}, {%4,%5,%6,%7}, {%8,%9}, {%0,%1,%2,%3};"
        : "+f"(c[0]), "+f"(c[1]), "+f"(c[2]), "+f"(c[3])
        : "r"(a.x), "r"(a.y), "r"(a.z), "r"(a.w), "r"(b0), "r"(b1));
}
__device__ __forceinline__ uint32_t h2u(float lo, float hi) {
    __half2 h = __floats2half2_rn(lo, hi);
    return *reinterpret_cast<uint32_t*>(&h);
}
#define CP_ASYNC_4(dst, src) \
    asm volatile("cp.async.ca.shared.global [%0], [%1], 4;" :: "r"(dst), "l"(src) : "memory")
#define CP_ASYNC_16(dst, src) \
    asm volatile("cp.async.cg.shared.global [%0], [%1], 16;" :: "r"(dst), "l"(src) : "memory")
#define CP_COMMIT() asm volatile("cp.async.commit_group;" ::: "memory")
#define CP_WAIT(n)  asm volatile("cp.async.wait_group %0;" :: "n"(n) : "memory")

// ---------------- smem maps (bytes) ----------------
// XB: two 16KB K=64 layer-1 chunk slots (later X3 full layout). WB: two 16KB W ring slots.
#define XB_B    0
#define WB_B    32768
#define SROW_B  65536
#define SCOL_B  66048
#define SDX_B   66560
#define SDY_B   67072
#define SDZ_B   67584
#define SID_B   68096
#define SDIST_B 68608
#define W257_B  69120
#define SWC2_B  69632
#define SBE1_B  70144
#define SBE2_B  70656
#define SBC1_B  71168
#define EDGE_SMEM_BYTES 71680

#define NWB_B   32768
#define NBN1_B  65536
#define NBN2_B  66048
#define NODE_SMEM_BYTES 66560

// ---------------- small kernels ----------------
__global__ void egnn_detect_kernel(const int* __restrict__ ei32) {
    int is64 = 1;
#pragma unroll
    for (int i = 1; i < 64; i += 2)
        if (ei32[i] != 0) is64 = 0;
    g_is64 = is64;
}

__global__ void egnn_init_kernel(const float* __restrict__ pos, const float* __restrict__ h,
                                 float* __restrict__ pos_out,
                                 long long nAgg, long long nPos) {
    long long i = (long long)blockIdx.x * blockDim.x + threadIdx.x;
    if (i < nAgg) { g_agg16[i] = __float2half(0.0f); g_h16[i] = __float2half(h[i]); }
    if (i < nPos) pos_out[i] = pos[i];
}

// fp16 B-fragment chunk images (identical encoding to R9-R16 — proven).
__global__ void egnn_prep_w(const float* __restrict__ We1, const float* __restrict__ We2,
                            const float* __restrict__ Wc1, const float* __restrict__ Wn1,
                            const float* __restrict__ Wn2) {
    int i = blockIdx.x * 256 + threadIdx.x;
    if (i >= 14 * 8192) return;
    int ci = i >> 13;
    int r = i & 8191;
    int rec = r >> 8;
    int lane = (r >> 3) & 31;
    int sub = r & 7;
    int ntp = rec >> 2, ks = rec & 3;
    int g = lane >> 2, tig = lane & 3;
    int n = (ntp * 2 + (sub >> 2)) * 8 + g;
    int k = ks * 16 + ((sub >> 1) & 1) * 8 + 2 * tig + (sub & 1);
    const float* W; int k0;
    if (ci < 4)       { W = We1; k0 = ci * 64; }
    else if (ci < 6)  { W = We2; k0 = (ci - 4) * 64; }
    else if (ci < 8)  { W = Wc1; k0 = (ci - 6) * 64; }
    else if (ci < 12) { W = Wn1; k0 = (ci - 8) * 64; }
    else              { W = Wn2; k0 = (ci - 12) * 64; }
    g_wimg16[ci * 8192 + rec * 256 + slot_of(lane) * 8 + sub] =
        __float2half(W[(k0 + k) * DD + n]);
}

// ---------------- mma cores: warp tile = 2 etiles x FULL 128 n ----------------
__device__ __forceinline__ void mma_l1(float (&C)[2][16][4], uint32_t xa0, uint32_t xa1,
                                       uint32_t wimg_u, uint32_t slot16) {
#pragma unroll
    for (int ks = 0; ks < 4; ks++) {
        uint4 a0 = lds128(xa0 + (uint32_t)(ks << 9) + slot16);
        uint4 a1 = lds128(xa1 + (uint32_t)(ks << 9) + slot16);
#pragma unroll
        for (int ntp = 0; ntp < 8; ntp++) {
            uint4 b = lds128(wimg_u + (uint32_t)(((ntp * 4 + ks) << 9)) + slot16);
            mma16(C[0][2 * ntp],     a0, b.x, b.y);
            mma16(C[0][2 * ntp + 1], a0, b.z, b.w);
            mma16(C[1][2 * ntp],     a1, b.x, b.y);
            mma16(C[1][2 * ntp + 1], a1, b.z, b.w);
        }
    }
}

__device__ __forceinline__ void mma_reg(float (&C)[2][16][4], uint4 (&A)[2][8],
                                        uint32_t wb0, uint32_t slot16) {
#pragma unroll
    for (int ks = 0; ks < 8; ks++) {
        uint32_t wimg = wb0 + (uint32_t)((ks >> 2) * 16384);
        int ksl = ks & 3;
#pragma unroll
        for (int ntp = 0; ntp < 8; ntp++) {
            uint4 b = lds128(wimg + (uint32_t)(((ntp * 4 + ksl) << 9)) + slot16);
            mma16(C[0][2 * ntp],     A[0][ks], b.x, b.y);
            mma16(C[0][2 * ntp + 1], A[0][ks], b.z, b.w);
            mma16(C[1][2 * ntp],     A[1][ks], b.x, b.y);
            mma16(C[1][2 * ntp + 1], A[1][ks], b.z, b.w);
        }
    }
}

__device__ __forceinline__ void stageW(uint32_t wbuf_u, const __half* __restrict__ img, int t) {
#pragma unroll
    for (int i = 0; i < 8; i++)
        CP_ASYNC_16(wbuf_u + (uint32_t)((i * 128 + t) * 16), (const char*)(img + (i * 128 + t) * 8));
}

__device__ __forceinline__ void gatherX(uint32_t xbuf_u, int c, int w, int g, int tig,
                                        uint32_t slot16, const __half* __restrict__ hb,
                                        const int* srow, const int* scol) {
#pragma unroll
    for (int mtl = 0; mtl < 2; mtl++) {
        int etile = 2 * w + mtl;
        int nlo = (c < 2 ? srow : scol)[etile * 16 + g];
        int nhi = (c < 2 ? srow : scol)[etile * 16 + g + 8];
        const __half* slo = hb + (long long)nlo * DD + (c & 1) * 64 + 2 * tig;
        const __half* shi = hb + (long long)nhi * DD + (c & 1) * 64 + 2 * tig;
#pragma unroll
        for (int ks = 0; ks < 4; ks++) {
            uint32_t rec = xbuf_u + (uint32_t)(((etile * 4 + ks) << 9)) + slot16;
            CP_ASYNC_4(rec + 0,  (const char*)(slo + ks * 16));
            CP_ASYNC_4(rec + 4,  (const char*)(shi + ks * 16));
            CP_ASYNC_4(rec + 8,  (const char*)(slo + ks * 16 + 8));
            CP_ASYNC_4(rec + 12, (const char*)(shi + ks * 16 + 8));
        }
    }
}

__device__ __forceinline__ void gatherN(uint32_t xbuf_u, const __half* __restrict__ hb,
                                        long long n0, long long Nn, int w, int g, int tig,
                                        uint32_t slot16) {
#pragma unroll
    for (int mtl = 0; mtl < 2; mtl++) {
        int etile = 2 * w + mtl;
        long long rlo = n0 + etile * 16 + g;     if (rlo >= Nn) rlo = Nn - 1;
        long long rhi = n0 + etile * 16 + g + 8; if (rhi >= Nn) rhi = Nn - 1;
        const __half* slo = hb + rlo * DD + 2 * tig;
        const __half* shi = hb + rhi * DD + 2 * tig;
#pragma unroll
        for (int ks = 0; ks < 4; ks++) {
            uint32_t rec = xbuf_u + (uint32_t)(((etile * 4 + ks) << 9)) + slot16;
            CP_ASYNC_4(rec + 0,  (const char*)(slo + ks * 16));
            CP_ASYNC_4(rec + 4,  (const char*)(shi + ks * 16));
            CP_ASYNC_4(rec + 8,  (const char*)(slo + ks * 16 + 8));
            CP_ASYNC_4(rec + 12, (const char*)(shi + ks * 16 + 8));
        }
    }
}

#define CLEAR_C() \
    _Pragma("unroll") for (int mt = 0; mt < 2; mt++) \
    _Pragma("unroll") for (int nt = 0; nt < 16; nt++) \
    _Pragma("unroll") for (int q = 0; q < 4; q++) C[mt][nt][q] = 0.0f

// ================= edge kernel =================
__global__ __launch_bounds__(128, 2) void egnn_edge_mma(
    const float* __restrict__ pos, const int* __restrict__ ei32, long long E,
    const float* __restrict__ We1, const float* __restrict__ be1,
    const float* __restrict__ be2, const float* __restrict__ bc1,
    const float* __restrict__ Wc2, float* __restrict__ pos_out)
{
    extern __shared__ __align__(16) float smem[];
    char* sb = (char*)smem;
    const uint32_t sbase = smem_u32(smem);
    int*   srow  = (int*)(sb + SROW_B);
    int*   scol  = (int*)(sb + SCOL_B);
    float* sdx   = (float*)(sb + SDX_B);
    float* sdy   = (float*)(sb + SDY_B);
    float* sdz   = (float*)(sb + SDZ_B);
    float* sid   = (float*)(sb + SID_B);
    float* sdist = (float*)(sb + SDIST_B);
    float* w257s = (float*)(sb + W257_B);
    float* swc2  = (float*)(sb + SWC2_B);
    float* sbe1  = (float*)(sb + SBE1_B);
    float* sbe2  = (float*)(sb + SBE2_B);
    float* sbc1  = (float*)(sb + SBC1_B);

    const int t = threadIdx.x;
    const int w = t >> 5;
    const int lane = t & 31;
    const int g = lane >> 2;
    const int tig = lane & 3;
    const int e0t = 2 * w;
    const uint32_t slot16 = (uint32_t)(slot_of(lane) * 16);
    const long long e0 = (long long)blockIdx.x * EPB;

    {   // edge meta + tables (one edge per thread)
        long long e = e0 + t;
        if (e >= E) e = E - 1;
        int r, c;
        if (g_is64) { r = ei32[2 * e]; c = ei32[2 * (E + e)]; }
        else        { r = ei32[e];     c = ei32[E + e]; }
        srow[t] = r; scol[t] = c;
        float dx = pos[r * 3 + 0] - pos[c * 3 + 0];
        float dy = pos[r * 3 + 1] - pos[c * 3 + 1];
        float dz = pos[r * 3 + 2] - pos[c * 3 + 2];
        float d = sqrtf(dx * dx + dy * dy + dz * dz);
        d = fmaxf(d, 1e-6f);
        sdx[t] = dx; sdy[t] = dy; sdz[t] = dz;
        sid[t] = 1.0f / d; sdist[t] = d;
        w257s[t] = We1[256 * DD + t];
        swc2[t]  = Wc2[t];
        sbe1[t]  = be1[t];
        sbe2[t]  = be2[t];
        sbc1[t]  = bc1[t];
    }
    __syncthreads();

    float C[2][16][4];
    uint4 Af[2][8];
    const uint32_t xb0 = sbase + XB_B;
    const uint32_t wb0 = sbase + WB_B;

    // ---------- layer 1: K=256, 4 pipelined K=64 chunks ----------
    CLEAR_C();
    stageW(wb0, g_wimg16 + 0 * 8192, t);
    gatherX(xb0, 0, w, g, tig, slot16, g_h16, srow, scol);
    CP_COMMIT();
    stageW(wb0 + 16384, g_wimg16 + 1 * 8192, t);
    gatherX(xb0 + 16384, 1, w, g, tig, slot16, g_h16, srow, scol);
    CP_COMMIT();

#pragma unroll
    for (int c = 0; c < 4; c++) {
        if (c < 3) CP_WAIT(1); else CP_WAIT(0);
        __syncthreads();
        uint32_t bx = xb0 + (uint32_t)((c & 1) * 16384);
        mma_l1(C, bx + (uint32_t)((e0t * 4) << 9), bx + (uint32_t)(((e0t + 1) * 4) << 9),
               wb0 + (uint32_t)((c & 1) * 16384), slot16);
        __syncthreads();
        if (c < 2) {
            stageW(wb0 + (uint32_t)((c & 1) * 16384), g_wimg16 + (c + 2) * 8192, t);
            gatherX(xb0 + (uint32_t)((c & 1) * 16384), c + 2, w, g, tig, slot16,
                    g_h16, srow, scol);
            CP_COMMIT();
        }
    }

    stageW(wb0, g_wimg16 + 4 * 8192, t);
    stageW(wb0 + 16384, g_wimg16 + 5 * 8192, t);
    CP_COMMIT();

    // epilogue 1: + dist*w257 + be1, silu -> Af (registers only)
#pragma unroll
    for (int mt = 0; mt < 2; mt++) {
        int etile = e0t + mt;
        float dlo = sdist[etile * 16 + g];
        float dhi = sdist[etile * 16 + g + 8];
#pragma unroll
        for (int l = 0; l < 8; l++) {
            int nt0 = 2 * l, nt1 = nt0 + 1;
            int n00 = nt0 * 8 + 2 * tig, n01 = n00 + 1;
            int n10 = nt1 * 8 + 2 * tig, n11 = n10 + 1;
            float w00 = w257s[n00], w01 = w257s[n01], w10 = w257s[n10], w11 = w257s[n11];
            float b00 = sbe1[n00], b01 = sbe1[n01], b10 = sbe1[n10], b11 = sbe1[n11];
            uint4 v;
            v.x = h2u(silu_f(C[mt][nt0][0] + dlo * w00 + b00), silu_f(C[mt][nt0][1] + dlo * w01 + b01));
            v.y = h2u(silu_f(C[mt][nt0][2] + dhi * w00 + b00), silu_f(C[mt][nt0][3] + dhi * w01 + b01));
            v.z = h2u(silu_f(C[mt][nt1][0] + dlo * w10 + b10), silu_f(C[mt][nt1][1] + dlo * w11 + b11));
            v.w = h2u(silu_f(C[mt][nt1][2] + dhi * w10 + b10), silu_f(C[mt][nt1][3] + dhi * w11 + b11));
            Af[mt][l] = v;
        }
    }
    CP_WAIT(0);
    __syncthreads();   // layer-2 weights visible

    // ---------- layer 2: K=128, A register-resident ----------
    CLEAR_C();
    mma_reg(C, Af, wb0, slot16);
    __syncthreads();   // all warps done reading layer-2 W

    stageW(wb0, g_wimg16 + 6 * 8192, t);
    stageW(wb0 + 16384, g_wimg16 + 7 * 8192, t);
    CP_COMMIT();

    // epilogue 2: msg = silu(C + be2) -> Af (regs) + X3 smem copy for scatter
#pragma unroll
    for (int mt = 0; mt < 2; mt++) {
        int etile = e0t + mt;
#pragma unroll
        for (int l = 0; l < 8; l++) {
            int nt0 = 2 * l, nt1 = nt0 + 1;
            int n00 = nt0 * 8 + 2 * tig, n01 = n00 + 1;
            int n10 = nt1 * 8 + 2 * tig, n11 = n10 + 1;
            float b00 = sbe2[n00], b01 = sbe2[n01], b10 = sbe2[n10], b11 = sbe2[n11];
            uint4 v;
            v.x = h2u(silu_f(C[mt][nt0][0] + b00), silu_f(C[mt][nt0][1] + b01));
            v.y = h2u(silu_f(C[mt][nt0][2] + b00), silu_f(C[mt][nt0][3] + b01));
            v.z = h2u(silu_f(C[mt][nt1][0] + b10), silu_f(C[mt][nt1][1] + b11));
            v.w = h2u(silu_f(C[mt][nt1][2] + b10), silu_f(C[mt][nt1][3] + b11));
            Af[mt][l] = v;
            sts128(xb0 + (uint32_t)(((etile * 8 + l) << 9)) + slot16, v);
        }
    }
    CP_WAIT(0);
    __syncthreads();   // X3 + layer-3 weights visible

    // ---------- layer 3: K=128, A register-resident ----------
    CLEAR_C();
    mma_reg(C, Af, wb0, slot16);

    // agg scatter from X3 as half2 atomics (thread t: feature pair 2jp..2jp+1, 64 edges)
    {
        int jp = t & 63;
        int eh = t >> 6;
        int n0f = 2 * jp;
        int kcol = n0f & 15;
        int tigp = (kcol & 7) >> 1;
        int regp = (kcol >> 3) * 2;
        int ks2 = n0f >> 4;
        int offs[16];
#pragma unroll
        for (int r = 0; r < 16; r++) {
            int lanep = (r & 7) * 4 + tigp;
            offs[r] = ks2 * 128 + slot_of(lanep) * 4 + regp + (r >> 3);   // uint32 index
        }
        const uint32_t xw0 = xb0;   // X3 records as uint32s via smem loads
        __half2* aggj = reinterpret_cast<__half2*>(g_agg16) + jp;
        if (e0 + EPB <= E) {
#pragma unroll 2
            for (int eq2 = 0; eq2 < 4; eq2++) {
                int eq = eh * 4 + eq2;
                int base = eq * 1024;
                int ewb = eq * 16;
#pragma unroll
                for (int r = 0; r < 16; r++) {
                    uint32_t mv = lds32(xw0 + (uint32_t)((base + offs[r]) * 4));
                    __half2 hv = *reinterpret_cast<__half2*>(&mv);
                    atomicAdd(aggj + (long long)srow[ewb + r] * 64, hv);
                }
            }
        } else {
#pragma unroll 2
            for (int el = 0; el < 64; el++) {
                int ew = eh * 64 + el;
                if (e0 + ew < E) {
                    uint32_t mv = lds32(xw0 + (uint32_t)(((ew >> 4) * 1024 + offs[ew & 15]) * 4));
                    __half2 hv = *reinterpret_cast<__half2*>(&mv);
                    atomicAdd(aggj + (long long)srow[ew] * 64, hv);
                }
            }
        }
    }

    // coord epilogue: warp-local reduce -> pos atomics
    {
        float sp[2][2] = {{0.f, 0.f}, {0.f, 0.f}};
#pragma unroll
        for (int mt = 0; mt < 2; mt++)
#pragma unroll
            for (int nt = 0; nt < 16; nt++)
#pragma unroll
                for (int q = 0; q < 4; q++) {
                    int n = nt * 8 + 2 * tig + (q & 1);
                    sp[mt][q >> 1] += silu_f(C[mt][nt][q] + sbc1[n]) * swc2[n];
                }
#pragma unroll
        for (int mt = 0; mt < 2; mt++)
#pragma unroll
            for (int hb = 0; hb < 2; hb++) {
                float s = sp[mt][hb];
                s += __shfl_xor_sync(0xFFFFFFFFu, s, 1);
                s += __shfl_xor_sync(0xFFFFFFFFu, s, 2);
                sp[mt][hb] = s;
            }
        if (tig == 0) {
#pragma unroll
            for (int mt = 0; mt < 2; mt++)
#pragma unroll
                for (int hb = 0; hb < 2; hb++) {
                    int ew = (e0t + mt) * 16 + g + 8 * hb;
                    if (e0 + ew < E) {
                        float s = fminf(fmaxf(sp[mt][hb], -1.0f), 1.0f);
                        float fac = s * sid[ew];
                        long long rr = srow[ew];
                        atomicAdd(&pos_out[rr * 3 + 0], sdx[ew] * fac);
                        atomicAdd(&pos_out[rr * 3 + 1], sdy[ew] * fac);
                        atomicAdd(&pos_out[rr * 3 + 2], sdz[ew] * fac);
                    }
                }
        }
    }
}

// ================= node kernel =================
__global__ __launch_bounds__(128, 2) void egnn_node_mma(
    const float* __restrict__ h,
    const float* __restrict__ bn1, const float* __restrict__ bn2,
    float* __restrict__ h_out, long long N)
{
    extern __shared__ __align__(16) float smem[];
    char* sb = (char*)smem;
    const uint32_t sbase = smem_u32(smem);
    float* sbn1 = (float*)(sb + NBN1_B);
    float* sbn2 = (float*)(sb + NBN2_B);

    const int t = threadIdx.x;
    const int w = t >> 5;
    const int lane = t & 31;
    const int g = lane >> 2;
    const int tig = lane & 3;
    const int e0t = 2 * w;
    const uint32_t slot16 = (uint32_t)(slot_of(lane) * 16);
    const long long n0 = (long long)blockIdx.x * EPB;

    sbn1[t] = bn1[t];
    sbn2[t] = bn2[t];
    __syncthreads();

    float C[2][16][4];
    uint4 Af[2][8];
    const uint32_t xb0 = sbase + XB_B;
    const uint32_t wb0 = sbase + NWB_B;

    // layer A: K=256 ([h16 ; agg16]), 4 pipelined chunks
    CLEAR_C();
    stageW(wb0, g_wimg16 + 8 * 8192, t);
    gatherN(xb0, g_h16, n0, N, w, g, tig, slot16);
    CP_COMMIT();
    stageW(wb0 + 16384, g_wimg16 + 9 * 8192, t);
    gatherN(xb0 + 16384, g_h16 + 64, n0, N, w, g, tig, slot16);
    CP_COMMIT();

#pragma unroll
    for (int c = 0; c < 4; c++) {
        if (c < 3) CP_WAIT(1); else CP_WAIT(0);
        __syncthreads();
        uint32_t bx = xb0 + (uint32_t)((c & 1) * 16384);
        mma_l1(C, bx + (uint32_t)((e0t * 4) << 9), bx + (uint32_t)(((e0t + 1) * 4) << 9),
               wb0 + (uint32_t)((c & 1) * 16384), slot16);
        __syncthreads();
        if (c < 2) {
            const __half* base = g_agg16 + (c & 1) * 64;
            stageW(wb0 + (uint32_t)((c & 1) * 16384), g_wimg16 + (10 + c) * 8192, t);
            gatherN(xb0 + (uint32_t)((c & 1) * 16384), base, n0, N, w, g, tig, slot16);
            CP_COMMIT();
        }
    }

    stageW(wb0, g_wimg16 + 12 * 8192, t);
    stageW(wb0 + 16384, g_wimg16 + 13 * 8192, t);
    CP_COMMIT();

    // epilogue A: silu(C + bn1) -> Af (registers only)
#pragma unroll
    for (int mt = 0; mt < 2; mt++) {
#pragma unroll
        for (int l = 0; l < 8; l++) {
            int nt0 = 2 * l, nt1 = nt0 + 1;
            int n00 = nt0 * 8 + 2 * tig, n01 = n00 + 1;
            int n10 = nt1 * 8 + 2 * tig, n11 = n10 + 1;
            float b00 = sbn1[n00], b01 = sbn1[n01], b10 = sbn1[n10], b11 = sbn1[n11];
            uint4 v;
            v.x = h2u(silu_f(C[mt][nt0][0] + b00), silu_f(C[mt][nt0][1] + b01));
            v.y = h2u(silu_f(C[mt][nt0][2] + b00), silu_f(C[mt][nt0][3] + b01));
            v.z = h2u(silu_f(C[mt][nt1][0] + b10), silu_f(C[mt][nt1][1] + b11));
            v.w = h2u(silu_f(C[mt][nt1][2] + b10), silu_f(C[mt][nt1][3] + b11));
            Af[mt][l] = v;
        }
    }
    CP_WAIT(0);
    __syncthreads();

    // layer B: K=128, A register-resident
    CLEAR_C();
    mma_reg(C, Af, wb0, slot16);

    // epilogue B: h_out = h + C + bn2 (direct float2 gmem)
#pragma unroll
    for (int mt = 0; mt < 2; mt++) {
        int etile = e0t + mt;
#pragma unroll
        for (int nt = 0; nt < 16; nt++) {
            int n = nt * 8 + 2 * tig;
            float b0 = sbn2[n], b1 = sbn2[n + 1];
#pragma unroll
            for (int qh = 0; qh < 2; qh++) {
                long long node = n0 + etile * 16 + g + 8 * qh;
                if (node < N) {
                    float2 hv = *reinterpret_cast<const float2*>(h + node * DD + n);
                    float2 o;
                    o.x = hv.x + C[mt][nt][2 * qh + 0] + b0;
                    o.y = hv.y + C[mt][nt][2 * qh + 1] + b1;
                    *reinterpret_cast<float2*>(h_out + node * DD + n) = o;
                }
            }
        }
    }
}

// ---------------- launcher ----------------
extern "C" void kernel_launch(void* const* d_in, const int* in_sizes, int n_in,
                              void* d_out, int out_size)
{
    const float* h   = (const float*)d_in[0];
    const float* pos = (const float*)d_in[1];
    const int*   ei  = (const int*)d_in[2];
    const float* We1 = (const float*)d_in[3];
    const float* be1 = (const float*)d_in[4];
    const float* We2 = (const float*)d_in[5];
    const float* be2 = (const float*)d_in[6];
    const float* Wn1 = (const float*)d_in[7];
    const float* bn1 = (const float*)d_in[8];
    const float* Wn2 = (const float*)d_in[9];
    const float* bn2 = (const float*)d_in[10];
    const float* Wc1 = (const float*)d_in[11];
    const float* bc1 = (const float*)d_in[12];
    const float* Wc2 = (const float*)d_in[13];

    const long long N = in_sizes[0] / DD;
    const long long E = (long long)in_sizes[2] / 2;

    float* h_out   = (float*)d_out;
    float* pos_out = h_out + N * DD;

    cudaFuncSetAttribute(egnn_edge_mma, cudaFuncAttributeMaxDynamicSharedMemorySize, EDGE_SMEM_BYTES);
    cudaFuncSetAttribute(egnn_node_mma, cudaFuncAttributeMaxDynamicSharedMemorySize, NODE_SMEM_BYTES);

    egnn_detect_kernel<<<1, 1>>>(ei);
    egnn_prep_w<<<(14 * 8192 + 255) / 256, 256>>>(We1, We2, Wc1, Wn1, Wn2);

    long long nAgg = N * DD;
    long long nPos = N * 3;
    egnn_init_kernel<<<(int)((nAgg + 255) / 256), 256>>>(pos, h, pos_out, nAgg, nPos);

    int eb = (int)((E + EPB - 1) / EPB);
    egnn_edge_mma<<<eb, 128, EDGE_SMEM_BYTES>>>(
        pos, ei, E, We1, be1, be2, bc1, Wc2, pos_out);

    int nb = (int)((N + EPB - 1) / EPB);
    egnn_node_mma<<<nb, 128, NODE_SMEM_BYTES>>>(
        h, bn1, bn2, h_out, N);
}